// round 3
// baseline (speedup 1.0000x reference)
#include <cuda_runtime.h>

// ---------------- problem constants ----------------
#define NP   100000
#define NA   200000
#define NSU  1000
#define NTOT (NP + NA + NSU)          // 301000
#define D    64
#define HOPS 5
#define NOUT 16

#define E_PA 800000
#define E_AP 800000
#define E_PS 100000
#define E_SP 100000
#define E_TOT (E_PA + E_AP + E_PS + E_SP)   // 1800000

// row_ptr segment bases (each segment length = Ns+1)
#define RP_PA 0
#define RP_AP (NP + 1)                 // 100001
#define RP_PS (RP_AP + NA + 1)         // 300002
#define RP_SP (RP_PS + NP + 1)         // 400003
#define RP_TOT (RP_SP + NSU + 1)       // 401004

// col array bases
#define CB_PA 0
#define CB_AP E_PA
#define CB_PS (E_PA + E_AP)
#define CB_SP (E_PA + E_AP + E_PS)

// h1 (target-side attention score) bases
#define H1_PA 0                        // len NA  (targets: author)
#define H1_AP NA                       // len NP  (targets: paper)
#define H1_PS (NA + NP)                // len NSU (targets: subject)
#define H1_SP (NA + NP + NSU)          // len NP  (targets: paper)
#define H1_TOT (NA + NP + NSU + NP)    // 401000

// ---------------- scratch (static device memory; no runtime alloc) ----------------
__device__ float g_x [NTOT * D];   // projected input features (constant across hops)
__device__ float g_hA[NTOT * D];   // h double buffer A
__device__ float g_hB[NTOT * D];   // h double buffer B
__device__ float g_h1[H1_TOT];     // per-edge-type target attention scores (per hop)
__device__ int   g_rowptr[RP_TOT];
__device__ int   g_cursor[RP_TOT];
__device__ int   g_col[E_TOT];

// ---------------- fc1: Y = relu(X @ W^T + b), writes g_x and g_hA ----------------
// X: [N, F] row-major, W: [64, F] row-major (torch layout). Tile 128x64, BK=16.
__global__ void fc1_kernel(const float* __restrict__ X, const float* __restrict__ W,
                           const float* __restrict__ bias, int N, int F, int nodeBase)
{
    __shared__ float As[16][132];  // [f][m], padded for bank conflicts, 4-word aligned rows
    __shared__ float Ws[16][68];   // [f][n]
    const int tid = threadIdx.x;          // 256 threads
    const int tx = tid & 15;              // output-col group (4 cols)
    const int ty = tid >> 4;              // output-row group (8 rows)
    const int bm0 = blockIdx.x * 128;

    float acc[8][4];
#pragma unroll
    for (int i = 0; i < 8; i++)
#pragma unroll
        for (int j = 0; j < 4; j++) acc[i][j] = 0.f;

    for (int k0 = 0; k0 < F; k0 += 16) {
        // load A tile 128x16 (8 elems/thread), coalesced along F
#pragma unroll
        for (int rr = 0; rr < 8; rr++) {
            int r = ty + rr * 16;
            int row = bm0 + r;
            As[tx][r] = (row < N) ? X[(long)row * F + k0 + tx] : 0.f;
        }
        // load W tile 16x64 (4 elems/thread)
#pragma unroll
        for (int jj = 0; jj < 4; jj++) {
            int j = ty + jj * 16;
            Ws[tx][j] = W[(long)j * F + k0 + tx];
        }
        __syncthreads();
#pragma unroll
        for (int f = 0; f < 16; f++) {
            float4 m0 = *(const float4*)&As[f][ty * 8];
            float4 m1 = *(const float4*)&As[f][ty * 8 + 4];
            float4 nn = *(const float4*)&Ws[f][tx * 4];
            float rm[8] = {m0.x, m0.y, m0.z, m0.w, m1.x, m1.y, m1.z, m1.w};
            float rn[4] = {nn.x, nn.y, nn.z, nn.w};
#pragma unroll
            for (int i = 0; i < 8; i++)
#pragma unroll
                for (int j = 0; j < 4; j++)
                    acc[i][j] += rm[i] * rn[j];
        }
        __syncthreads();
    }

#pragma unroll
    for (int i = 0; i < 8; i++) {
        int row = bm0 + ty * 8 + i;
        if (row < N) {
#pragma unroll
            for (int j = 0; j < 4; j++) {
                int col = tx * 4 + j;
                float v = acc[i][j] + bias[col];
                v = fmaxf(v, 0.f);
                long o = (long)(nodeBase + row) * D + col;
                g_x[o]  = v;
                g_hA[o] = v;
            }
        }
    }
}

// ---------------- CSR build ----------------
__global__ void zero_rowptr_kernel()
{
    int i = blockIdx.x * blockDim.x + threadIdx.x;
    if (i < RP_TOT) g_rowptr[i] = 0;
}

__global__ void hist_kernel(const int* __restrict__ ei_pa, const int* __restrict__ ei_ap,
                            const int* __restrict__ ei_ps, const int* __restrict__ ei_sp)
{
    int e = blockIdx.x * blockDim.x + threadIdx.x;
    if (e >= E_TOT) return;
    const int* ei; int l, rpb;
    if (e < E_PA)                  { ei = ei_pa; l = e;                     rpb = RP_PA; }
    else if (e < E_PA + E_AP)      { ei = ei_ap; l = e - E_PA;              rpb = RP_AP; }
    else if (e < E_PA + E_AP + E_PS){ ei = ei_ps; l = e - E_PA - E_AP;      rpb = RP_PS; }
    else                           { ei = ei_sp; l = e - E_PA - E_AP - E_PS; rpb = RP_SP; }
    atomicAdd(&g_rowptr[rpb + 1 + ei[l]], 1);
}

// one block per edge-type segment: in-place inclusive scan of [0, d0, d1, ...],
// result: rowptr[base+j] = start offset of node j; also copies into g_cursor.
__global__ void scan_kernel()
{
    __shared__ int ssum[1024];
    int base, n;
    if (blockIdx.x == 0)      { base = RP_PA; n = NP + 1;  }
    else if (blockIdx.x == 1) { base = RP_AP; n = NA + 1;  }
    else if (blockIdx.x == 2) { base = RP_PS; n = NP + 1;  }
    else                      { base = RP_SP; n = NSU + 1; }
    int tid = threadIdx.x;
    int chunk = (n + 1023) >> 10;
    int s0 = tid * chunk;
    int s1 = s0 + chunk; if (s1 > n) s1 = n; if (s0 > n) s0 = n;

    int sum = 0;
    for (int j = s0; j < s1; j++) sum += g_rowptr[base + j];
    ssum[tid] = sum;
    __syncthreads();
    for (int off = 1; off < 1024; off <<= 1) {
        int v = (tid >= off) ? ssum[tid - off] : 0;
        __syncthreads();
        ssum[tid] += v;
        __syncthreads();
    }
    int run = (tid == 0) ? 0 : ssum[tid - 1];
    for (int j = s0; j < s1; j++) {
        run += g_rowptr[base + j];
        g_rowptr[base + j] = run;
        g_cursor[base + j] = run;
    }
}

__global__ void scatter_kernel(const int* __restrict__ ei_pa, const int* __restrict__ ei_ap,
                               const int* __restrict__ ei_ps, const int* __restrict__ ei_sp)
{
    int e = blockIdx.x * blockDim.x + threadIdx.x;
    if (e >= E_TOT) return;
    const int* ei; int l, rpb, cb, En;
    if (e < E_PA)                  { ei = ei_pa; l = e;                      rpb = RP_PA; cb = CB_PA; En = E_PA; }
    else if (e < E_PA + E_AP)      { ei = ei_ap; l = e - E_PA;               rpb = RP_AP; cb = CB_AP; En = E_AP; }
    else if (e < E_PA + E_AP + E_PS){ ei = ei_ps; l = e - E_PA - E_AP;       rpb = RP_PS; cb = CB_PS; En = E_PS; }
    else                           { ei = ei_sp; l = e - E_PA - E_AP - E_PS; rpb = RP_SP; cb = CB_SP; En = E_SP; }
    int s = ei[l];
    int t = ei[En + l];
    int pos = atomicAdd(&g_cursor[rpb + s], 1);
    g_col[cb + pos] = t;
}

// ---------------- per-hop: target-side attention scores h1 = h . a2 ----------------
__global__ void h1_kernel(const float* __restrict__ attn2, int hop, int curB)
{
    int gw = (blockIdx.x * blockDim.x + threadIdx.x) >> 5;
    int lane = threadIdx.x & 31;
    if (gw >= H1_TOT) return;
    const float* h = curB ? g_hB : g_hA;
    int k, node, outIdx;
    if (gw < NA)                 { k = 0; node = NP + gw;        outIdx = H1_PA + gw; }
    else if (gw < NA + NP)       { int l = gw - NA;       k = 1; node = l;            outIdx = H1_AP + l; }
    else if (gw < NA + NP + NSU) { int l = gw - NA - NP;  k = 2; node = NP + NA + l;  outIdx = H1_PS + l; }
    else                         { int l = gw - NA - NP - NSU; k = 3; node = l;       outIdx = H1_SP + l; }
    const float* a2 = attn2 + (hop * 4 + k) * D;
    const float* hr = h + (long)node * D;
    float v = hr[lane] * a2[lane] + hr[lane + 32] * a2[lane + 32];
#pragma unroll
    for (int o = 16; o; o >>= 1) v += __shfl_xor_sync(0xffffffffu, v, o);
    if (lane == 0) g_h1[outIdx] = v;
}

// ---------------- per-hop aggregation (warp per source node, gather form) ----------------
__device__ __forceinline__ float wsum32(float v)
{
#pragma unroll
    for (int o = 16; o; o >>= 1) v += __shfl_xor_sync(0xffffffffu, v, o);
    return v;
}

__device__ __forceinline__ void aggr_et(
    int k, int nodeLocal, int rpBase, int colBase, int h1Base, int tOff,
    const float* __restrict__ h, const float* __restrict__ attn1,
    const float* __restrict__ attn2, int hop, int lane,
    float x0, float x1, float wk, float& acc0, float& acc1)
{
    const float* a1 = attn1 + (hop * 4 + k) * D;
    const float* a2 = attn2 + (hop * 4 + k) * D;
    float d1 = wsum32(x0 * a1[lane] + x1 * a1[lane + 32]);   // x . a1
    float d2 = wsum32(x0 * a2[lane] + x1 * a2[lane + 32]);   // x . a2
    float z = d1 + d2;
    z = z > 0.f ? z : 0.2f * z;
    float w2 = expf(z);                                       // self term
    float num0 = w2 * x0, num1 = w2 * x1, div = w2;
    int e0 = g_rowptr[rpBase + nodeLocal];
    int e1 = g_rowptr[rpBase + nodeLocal + 1];
    for (int e = e0; e < e1; e++) {
        int t = g_col[colBase + e];
        float z1 = d1 + g_h1[h1Base + t];
        z1 = z1 > 0.f ? z1 : 0.2f * z1;
        float w1 = expf(z1);
        const float* hr = h + (long)(tOff + t) * D;
        num0 += w1 * hr[lane];
        num1 += w1 * hr[lane + 32];
        div  += w1;
    }
    float s = wk / div;
    acc0 += num0 * s;
    acc1 += num1 * s;
}

__global__ void aggr_kernel(const float* __restrict__ attn1, const float* __restrict__ attn2,
                            const float* __restrict__ lw, int hop, int curB)
{
    int gw = (blockIdx.x * blockDim.x + threadIdx.x) >> 5;
    int lane = threadIdx.x & 31;
    if (gw >= NTOT) return;
    const float* h  = curB ? g_hB : g_hA;
    float*       hn = curB ? g_hA : g_hB;
    const float* xr = g_x + (long)gw * D;
    float x0 = xr[lane], x1 = xr[lane + 32];
    float acc0 = 0.f, acc1 = 0.f;

    if (gw < NP) {
        // paper: edge types 0 (pa) and 2 (ps); softmax over lw[hop, {0,2}]
        float l0 = lw[hop * 4 + 0], l2 = lw[hop * 4 + 2];
        float m = fmaxf(l0, l2);
        float e0 = expf(l0 - m), e2 = expf(l2 - m);
        float inv = 1.f / (e0 + e2);
        aggr_et(0, gw, RP_PA, CB_PA, H1_PA, NP,      h, attn1, attn2, hop, lane, x0, x1, e0 * inv, acc0, acc1);
        aggr_et(2, gw, RP_PS, CB_PS, H1_PS, NP + NA, h, attn1, attn2, hop, lane, x0, x1, e2 * inv, acc0, acc1);
    } else if (gw < NP + NA) {
        aggr_et(1, gw - NP, RP_AP, CB_AP, H1_AP, 0,  h, attn1, attn2, hop, lane, x0, x1, 1.f, acc0, acc1);
    } else {
        aggr_et(3, gw - NP - NA, RP_SP, CB_SP, H1_SP, 0, h, attn1, attn2, hop, lane, x0, x1, 1.f, acc0, acc1);
    }
    // elu
    acc0 = acc0 > 0.f ? acc0 : expf(acc0) - 1.f;
    acc1 = acc1 > 0.f ? acc1 : expf(acc1) - 1.f;
    hn[(long)gw * D + lane]      = acc0;
    hn[(long)gw * D + lane + 32] = acc1;
}

// ---------------- fc2: out = h_paper @ W^T + b ----------------
__global__ void fc2_kernel(const float* __restrict__ W, const float* __restrict__ bias,
                           float* __restrict__ out)
{
    int idx = blockIdx.x * blockDim.x + threadIdx.x;
    if (idx >= NP * NOUT) return;
    int n = idx >> 4, o = idx & 15;
    const float* hr = g_hB + (long)n * D;   // HOPS=5 odd -> final h in buffer B
    const float* wr = W + o * D;
    float s = bias[o];
#pragma unroll
    for (int d = 0; d < D; d++) s += hr[d] * wr[d];
    out[idx] = s;
}

// ---------------- launch ----------------
extern "C" void kernel_launch(void* const* d_in, const int* in_sizes, int n_in,
                              void* d_out, int out_size)
{
    const float* x_paper   = (const float*)d_in[0];
    const float* x_author  = (const float*)d_in[1];
    const float* x_subject = (const float*)d_in[2];
    const float* fc1p_w = (const float*)d_in[3];
    const float* fc1p_b = (const float*)d_in[4];
    const float* fc1a_w = (const float*)d_in[5];
    const float* fc1a_b = (const float*)d_in[6];
    const float* fc1s_w = (const float*)d_in[7];
    const float* fc1s_b = (const float*)d_in[8];
    const float* attn1  = (const float*)d_in[9];
    const float* attn2  = (const float*)d_in[10];
    const float* lw     = (const float*)d_in[11];
    const float* fc2_w  = (const float*)d_in[12];
    const float* fc2_b  = (const float*)d_in[13];
    const int* ei_pa = (const int*)d_in[14];
    const int* ei_ap = (const int*)d_in[15];
    const int* ei_ps = (const int*)d_in[16];
    const int* ei_sp = (const int*)d_in[17];
    float* out = (float*)d_out;

    // CSR build (deterministic up to within-row ordering; FP tolerance covers it)
    zero_rowptr_kernel<<<(RP_TOT + 255) / 256, 256>>>();

    // input projection (also initializes h buffer A)
    fc1_kernel<<<(NP  + 127) / 128, 256>>>(x_paper,   fc1p_w, fc1p_b, NP,  512, 0);
    fc1_kernel<<<(NA  + 127) / 128, 256>>>(x_author,  fc1a_w, fc1a_b, NA,  256, NP);
    fc1_kernel<<<(NSU + 127) / 128, 256>>>(x_subject, fc1s_w, fc1s_b, NSU, 128, NP + NA);

    hist_kernel<<<(E_TOT + 255) / 256, 256>>>(ei_pa, ei_ap, ei_ps, ei_sp);
    scan_kernel<<<4, 1024>>>();
    scatter_kernel<<<(E_TOT + 255) / 256, 256>>>(ei_pa, ei_ap, ei_ps, ei_sp);

    for (int hop = 0; hop < HOPS; hop++) {
        int curB = hop & 1;   // hop even: read A write B; hop odd: read B write A
        h1_kernel  <<<(H1_TOT * 32 + 255) / 256, 256>>>(attn2, hop, curB);
        aggr_kernel<<<(NTOT   * 32 + 255) / 256, 256>>>(attn1, attn2, lw, hop, curB);
    }

    fc2_kernel<<<(NP * NOUT + 255) / 256, 256>>>(fc2_w, fc2_b, out);
}

// round 4
// speedup vs baseline: 1.3242x; 1.3242x over previous
#include <cuda_runtime.h>
#include <cstdint>

// ---------------- problem constants ----------------
#define NP   100000
#define NA   200000
#define NSU  1000
#define NTOT (NP + NA + NSU)          // 301000
#define D    64
#define HOPS 5
#define NOUT 16

#define E_PA 800000
#define E_AP 800000
#define E_PS 100000
#define E_SP 100000
#define E_TOT (E_PA + E_AP + E_PS + E_SP)   // 1800000

// row_ptr segment bases (each segment length = Ns+1)
#define RP_PA 0
#define RP_AP (NP + 1)
#define RP_PS (RP_AP + NA + 1)
#define RP_SP (RP_PS + NP + 1)
#define RP_TOT (RP_SP + NSU + 1)

// col array bases
#define CB_PA 0
#define CB_AP E_PA
#define CB_PS (E_PA + E_AP)
#define CB_SP (E_PA + E_AP + E_PS)

// h1 (target-side attention score) bases
#define H1_PA 0                        // len NA  (targets: author)
#define H1_AP NA                       // len NP  (targets: paper)
#define H1_PS (NA + NP)                // len NSU (targets: subject)
#define H1_SP (NA + NP + NSU)          // len NP  (targets: paper)
#define H1_TOT (NA + NP + NSU + NP)

// ---------------- scratch (static device memory; no runtime alloc) ----------------
__device__ float g_x [NTOT * D];
__device__ float g_hA[NTOT * D];
__device__ float g_hB[NTOT * D];
__device__ float g_h1[H1_TOT];
__device__ int   g_rowptr[RP_TOT];
__device__ int   g_cursor[RP_TOT];
__device__ int   g_col[E_TOT];

// ---------------- tf32 helpers ----------------
__device__ __forceinline__ uint32_t f2tf(float x)
{
    uint32_t r;
    asm("cvt.rna.tf32.f32 %0, %1;" : "=r"(r) : "f"(x));
    return r;
}

__device__ __forceinline__ void split_tf32(float x, float& hi, float& lo)
{
    uint32_t h = f2tf(x);
    float hf = __uint_as_float(h);
    hi = hf;
    lo = __uint_as_float(f2tf(x - hf));
}

#define MMA_TF32(c, a, b) \
    asm volatile("mma.sync.aligned.m16n8k8.row.col.f32.tf32.tf32.f32 " \
                 "{%0,%1,%2,%3},{%4,%5,%6,%7},{%8,%9},{%0,%1,%2,%3};" \
                 : "+f"((c)[0]), "+f"((c)[1]), "+f"((c)[2]), "+f"((c)[3]) \
                 : "r"(__float_as_uint((a)[0])), "r"(__float_as_uint((a)[1])), \
                   "r"(__float_as_uint((a)[2])), "r"(__float_as_uint((a)[3])), \
                   "r"(__float_as_uint((b)[0])), "r"(__float_as_uint((b)[1])))

// ---------------- fc1: Y = relu(X @ W^T + b) via tf32x3 tensor cores ----------------
// X: [N, F] row-major. W: [64, F] row-major (torch layout) == col-major [F, 64] -> mma row.col.
// Block tile: 128(M) x 64(N) x 32(K). 8 warps: warp_m in 0..3 (32 rows), warp_n in 0..1 (32 cols).
// Smem swizzle: element (row, col) stored at column (col + 4*row) & 31 -> conflict-free
// fragment loads (bank = (4*(row&7) + (col&3)) pattern is a bijection over 32 banks).
__global__ void __launch_bounds__(256) fc1_kernel(
    const float* __restrict__ X, const float* __restrict__ W,
    const float* __restrict__ bias, int N, int F, int nodeBase)
{
    __shared__ float Xhi[128][32];
    __shared__ float Xlo[128][32];
    __shared__ float Whi[64][32];
    __shared__ float Wlo[64][32];

    const int tid  = threadIdx.x;
    const int lane = tid & 31;
    const int warp = tid >> 5;
    const int warp_m = warp & 3;
    const int warp_n = warp >> 2;
    const int bm0 = blockIdx.x * 128;

    float c[2][4][4];
#pragma unroll
    for (int mt = 0; mt < 2; mt++)
#pragma unroll
        for (int nt = 0; nt < 4; nt++)
#pragma unroll
            for (int i = 0; i < 4; i++) c[mt][nt][i] = 0.f;

    const int lr = tid >> 3;          // 0..31: row within 32-row chunk
    const int lc = (tid & 7) * 4;     // 0,4,...,28: k offset

    for (int k0 = 0; k0 < F; k0 += 32) {
        // ---- load + split X tile (128 x 32) ----
#pragma unroll
        for (int i = 0; i < 4; i++) {
            int r = lr + i * 32;
            int row = bm0 + r;
            float4 v = make_float4(0.f, 0.f, 0.f, 0.f);
            if (row < N) v = *(const float4*)&X[(long)row * F + k0 + lc];
            int sc = (lc + 4 * r) & 31;
            float h0, l0, h1, l1, h2, l2, h3, l3;
            split_tf32(v.x, h0, l0); split_tf32(v.y, h1, l1);
            split_tf32(v.z, h2, l2); split_tf32(v.w, h3, l3);
            *(float4*)&Xhi[r][sc] = make_float4(h0, h1, h2, h3);
            *(float4*)&Xlo[r][sc] = make_float4(l0, l1, l2, l3);
        }
        // ---- load + split W tile (64 x 32) ----
#pragma unroll
        for (int i = 0; i < 2; i++) {
            int r = lr + i * 32;
            float4 v = *(const float4*)&W[(long)r * F + k0 + lc];
            int sc = (lc + 4 * r) & 31;
            float h0, l0, h1, l1, h2, l2, h3, l3;
            split_tf32(v.x, h0, l0); split_tf32(v.y, h1, l1);
            split_tf32(v.z, h2, l2); split_tf32(v.w, h3, l3);
            *(float4*)&Whi[r][sc] = make_float4(h0, h1, h2, h3);
            *(float4*)&Wlo[r][sc] = make_float4(l0, l1, l2, l3);
        }
        __syncthreads();

        const int ar = lane >> 2;   // 0..7
        const int ac = lane & 3;    // 0..3
#pragma unroll
        for (int ks = 0; ks < 4; ks++) {
            int kk = ks * 8;
            float ahi[2][4], alo[2][4], bhi[4][2], blo[4][2];
#pragma unroll
            for (int mt = 0; mt < 2; mt++) {
                int r0 = warp_m * 32 + mt * 16 + ar;
                int r1 = r0 + 8;
                int c0a = (kk + ac + 4 * r0) & 31;
                int c1a = (kk + ac + 4 * r1) & 31;
                int c0b = (kk + ac + 4 + 4 * r0) & 31;
                int c1b = (kk + ac + 4 + 4 * r1) & 31;
                ahi[mt][0] = Xhi[r0][c0a]; alo[mt][0] = Xlo[r0][c0a];
                ahi[mt][1] = Xhi[r1][c1a]; alo[mt][1] = Xlo[r1][c1a];
                ahi[mt][2] = Xhi[r0][c0b]; alo[mt][2] = Xlo[r0][c0b];
                ahi[mt][3] = Xhi[r1][c1b]; alo[mt][3] = Xlo[r1][c1b];
            }
#pragma unroll
            for (int nt = 0; nt < 4; nt++) {
                int n = warp_n * 32 + nt * 8 + ar;
                int c0a = (kk + ac + 4 * n) & 31;
                int c0b = (kk + ac + 4 + 4 * n) & 31;
                bhi[nt][0] = Whi[n][c0a]; blo[nt][0] = Wlo[n][c0a];
                bhi[nt][1] = Whi[n][c0b]; blo[nt][1] = Wlo[n][c0b];
            }
#pragma unroll
            for (int mt = 0; mt < 2; mt++)
#pragma unroll
                for (int nt = 0; nt < 4; nt++) {
                    MMA_TF32(c[mt][nt], ahi[mt], bhi[nt]);
                    MMA_TF32(c[mt][nt], ahi[mt], blo[nt]);
                    MMA_TF32(c[mt][nt], alo[mt], bhi[nt]);
                }
        }
        __syncthreads();
    }

    // ---- epilogue: bias + relu, write g_x and g_hA ----
#pragma unroll
    for (int mt = 0; mt < 2; mt++) {
#pragma unroll
        for (int nt = 0; nt < 4; nt++) {
            int row = bm0 + warp_m * 32 + mt * 16 + (lane >> 2);
            int col = warp_n * 32 + nt * 8 + (lane & 3) * 2;
            float b0 = __ldg(&bias[col]);
            float b1 = __ldg(&bias[col + 1]);
            if (row < N) {
                float v0 = fmaxf(c[mt][nt][0] + b0, 0.f);
                float v1 = fmaxf(c[mt][nt][1] + b1, 0.f);
                long o = (long)(nodeBase + row) * D + col;
                *(float2*)&g_x[o]  = make_float2(v0, v1);
                *(float2*)&g_hA[o] = make_float2(v0, v1);
            }
            if (row + 8 < N) {
                float v2 = fmaxf(c[mt][nt][2] + b0, 0.f);
                float v3 = fmaxf(c[mt][nt][3] + b1, 0.f);
                long o = (long)(nodeBase + row + 8) * D + col;
                *(float2*)&g_x[o]  = make_float2(v2, v3);
                *(float2*)&g_hA[o] = make_float2(v2, v3);
            }
        }
    }
}

// ---------------- CSR build ----------------
__global__ void zero_rowptr_kernel()
{
    int i = blockIdx.x * blockDim.x + threadIdx.x;
    if (i < RP_TOT) g_rowptr[i] = 0;
}

__global__ void hist_kernel(const int* __restrict__ ei_pa, const int* __restrict__ ei_ap,
                            const int* __restrict__ ei_ps, const int* __restrict__ ei_sp)
{
    int e = blockIdx.x * blockDim.x + threadIdx.x;
    if (e >= E_TOT) return;
    const int* ei; int l, rpb;
    if (e < E_PA)                   { ei = ei_pa; l = e;                      rpb = RP_PA; }
    else if (e < E_PA + E_AP)       { ei = ei_ap; l = e - E_PA;               rpb = RP_AP; }
    else if (e < E_PA + E_AP + E_PS){ ei = ei_ps; l = e - E_PA - E_AP;        rpb = RP_PS; }
    else                            { ei = ei_sp; l = e - E_PA - E_AP - E_PS; rpb = RP_SP; }
    atomicAdd(&g_rowptr[rpb + 1 + ei[l]], 1);
}

__global__ void scan_kernel()
{
    __shared__ int ssum[1024];
    int base, n;
    if (blockIdx.x == 0)      { base = RP_PA; n = NP + 1;  }
    else if (blockIdx.x == 1) { base = RP_AP; n = NA + 1;  }
    else if (blockIdx.x == 2) { base = RP_PS; n = NP + 1;  }
    else                      { base = RP_SP; n = NSU + 1; }
    int tid = threadIdx.x;
    int chunk = (n + 1023) >> 10;
    int s0 = tid * chunk;
    int s1 = s0 + chunk; if (s1 > n) s1 = n; if (s0 > n) s0 = n;

    int sum = 0;
    for (int j = s0; j < s1; j++) sum += g_rowptr[base + j];
    ssum[tid] = sum;
    __syncthreads();
    for (int off = 1; off < 1024; off <<= 1) {
        int v = (tid >= off) ? ssum[tid - off] : 0;
        __syncthreads();
        ssum[tid] += v;
        __syncthreads();
    }
    int run = (tid == 0) ? 0 : ssum[tid - 1];
    for (int j = s0; j < s1; j++) {
        run += g_rowptr[base + j];
        g_rowptr[base + j] = run;
        g_cursor[base + j] = run;
    }
}

__global__ void scatter_kernel(const int* __restrict__ ei_pa, const int* __restrict__ ei_ap,
                               const int* __restrict__ ei_ps, const int* __restrict__ ei_sp)
{
    int e = blockIdx.x * blockDim.x + threadIdx.x;
    if (e >= E_TOT) return;
    const int* ei; int l, rpb, cb, En;
    if (e < E_PA)                   { ei = ei_pa; l = e;                      rpb = RP_PA; cb = CB_PA; En = E_PA; }
    else if (e < E_PA + E_AP)       { ei = ei_ap; l = e - E_PA;               rpb = RP_AP; cb = CB_AP; En = E_AP; }
    else if (e < E_PA + E_AP + E_PS){ ei = ei_ps; l = e - E_PA - E_AP;        rpb = RP_PS; cb = CB_PS; En = E_PS; }
    else                            { ei = ei_sp; l = e - E_PA - E_AP - E_PS; rpb = RP_SP; cb = CB_SP; En = E_SP; }
    int s = ei[l];
    int t = ei[En + l];
    int pos = atomicAdd(&g_cursor[rpb + s], 1);
    g_col[cb + pos] = t;
}

// ---------------- per-hop: target-side attention scores h1 = h . a2 ----------------
__global__ void h1_kernel(const float* __restrict__ attn2, int hop, int curB)
{
    int gw = (blockIdx.x * blockDim.x + threadIdx.x) >> 5;
    int lane = threadIdx.x & 31;
    if (gw >= H1_TOT) return;
    const float* h = curB ? g_hB : g_hA;
    int k, node, outIdx;
    if (gw < NA)                 { k = 0; node = NP + gw;        outIdx = H1_PA + gw; }
    else if (gw < NA + NP)       { int l = gw - NA;       k = 1; node = l;            outIdx = H1_AP + l; }
    else if (gw < NA + NP + NSU) { int l = gw - NA - NP;  k = 2; node = NP + NA + l;  outIdx = H1_PS + l; }
    else                         { int l = gw - NA - NP - NSU; k = 3; node = l;       outIdx = H1_SP + l; }
    const float* a2 = attn2 + (hop * 4 + k) * D;
    const float* hr = h + (long)node * D;
    float v = hr[lane] * a2[lane] + hr[lane + 32] * a2[lane + 32];
#pragma unroll
    for (int o = 16; o; o >>= 1) v += __shfl_xor_sync(0xffffffffu, v, o);
    if (lane == 0) g_h1[outIdx] = v;
}

// ---------------- per-hop aggregation (warp per source node, gather, unroll x2) ------
__device__ __forceinline__ float wsum32(float v)
{
#pragma unroll
    for (int o = 16; o; o >>= 1) v += __shfl_xor_sync(0xffffffffu, v, o);
    return v;
}

__device__ __forceinline__ void aggr_et(
    int k, int nodeLocal, int rpBase, int colBase, int h1Base, int tOff,
    const float* __restrict__ h, const float* __restrict__ attn1,
    const float* __restrict__ attn2, int hop, int lane,
    float x0, float x1, float wk, float& acc0, float& acc1)
{
    const float* a1 = attn1 + (hop * 4 + k) * D;
    const float* a2 = attn2 + (hop * 4 + k) * D;
    float d1 = wsum32(x0 * a1[lane] + x1 * a1[lane + 32]);   // x . a1
    float d2 = wsum32(x0 * a2[lane] + x1 * a2[lane + 32]);   // x . a2
    float z = d1 + d2;
    z = z > 0.f ? z : 0.2f * z;
    float w2 = __expf(z);                                    // self term
    float num0 = w2 * x0, num1 = w2 * x1, div = w2;
    int e0 = g_rowptr[rpBase + nodeLocal];
    int e1 = g_rowptr[rpBase + nodeLocal + 1];
    int e = e0;
    for (; e + 2 <= e1; e += 2) {
        int t0 = g_col[colBase + e];
        int t1 = g_col[colBase + e + 1];
        float p0 = g_h1[h1Base + t0];
        float p1 = g_h1[h1Base + t1];
        const float* hr0 = h + (long)(tOff + t0) * D;
        const float* hr1 = h + (long)(tOff + t1) * D;
        float u0 = hr0[lane], u1 = hr0[lane + 32];
        float v0 = hr1[lane], v1 = hr1[lane + 32];
        float z0 = d1 + p0; z0 = z0 > 0.f ? z0 : 0.2f * z0;
        float z1 = d1 + p1; z1 = z1 > 0.f ? z1 : 0.2f * z1;
        float w0 = __expf(z0);
        float w1 = __expf(z1);
        num0 += w0 * u0 + w1 * v0;
        num1 += w0 * u1 + w1 * v1;
        div  += w0 + w1;
    }
    if (e < e1) {
        int t = g_col[colBase + e];
        float zz = d1 + g_h1[h1Base + t];
        zz = zz > 0.f ? zz : 0.2f * zz;
        float w1 = __expf(zz);
        const float* hr = h + (long)(tOff + t) * D;
        num0 += w1 * hr[lane];
        num1 += w1 * hr[lane + 32];
        div  += w1;
    }
    float s = wk / div;
    acc0 += num0 * s;
    acc1 += num1 * s;
}

__global__ void __launch_bounds__(256) aggr_kernel(
    const float* __restrict__ attn1, const float* __restrict__ attn2,
    const float* __restrict__ lw, int hop, int curB)
{
    int gw = (blockIdx.x * blockDim.x + threadIdx.x) >> 5;
    int lane = threadIdx.x & 31;
    if (gw >= NTOT) return;
    const float* h  = curB ? g_hB : g_hA;
    float*       hn = curB ? g_hA : g_hB;
    const float* xr = g_x + (long)gw * D;
    float x0 = xr[lane], x1 = xr[lane + 32];
    float acc0 = 0.f, acc1 = 0.f;

    if (gw < NP) {
        float l0 = lw[hop * 4 + 0], l2 = lw[hop * 4 + 2];
        float m = fmaxf(l0, l2);
        float e0 = __expf(l0 - m), e2 = __expf(l2 - m);
        float inv = 1.f / (e0 + e2);
        aggr_et(0, gw, RP_PA, CB_PA, H1_PA, NP,      h, attn1, attn2, hop, lane, x0, x1, e0 * inv, acc0, acc1);
        aggr_et(2, gw, RP_PS, CB_PS, H1_PS, NP + NA, h, attn1, attn2, hop, lane, x0, x1, e2 * inv, acc0, acc1);
    } else if (gw < NP + NA) {
        aggr_et(1, gw - NP, RP_AP, CB_AP, H1_AP, 0,  h, attn1, attn2, hop, lane, x0, x1, 1.f, acc0, acc1);
    } else {
        aggr_et(3, gw - NP - NA, RP_SP, CB_SP, H1_SP, 0, h, attn1, attn2, hop, lane, x0, x1, 1.f, acc0, acc1);
    }
    acc0 = acc0 > 0.f ? acc0 : __expf(acc0) - 1.f;
    acc1 = acc1 > 0.f ? acc1 : __expf(acc1) - 1.f;
    hn[(long)gw * D + lane]      = acc0;
    hn[(long)gw * D + lane + 32] = acc1;
}

// ---------------- fc2: out = h_paper @ W^T + b (warp per node, W in smem) -----------
__global__ void __launch_bounds__(256) fc2_kernel(
    const float* __restrict__ W, const float* __restrict__ bias,
    float* __restrict__ out)
{
    __shared__ float Ws[NOUT * D];
    __shared__ float bs[NOUT];
    int tid = threadIdx.x;
    for (int i = tid; i < NOUT * D; i += 256) Ws[i] = W[i];
    if (tid < NOUT) bs[tid] = bias[tid];
    __syncthreads();

    int gw = (blockIdx.x * 256 + tid) >> 5;
    int lane = tid & 31;
    if (gw >= NP) return;
    const float* hr = g_hB + (long)gw * D;   // HOPS=5 -> final h in buffer B
    float v0 = hr[lane], v1 = hr[lane + 32];
    float res = 0.f;
#pragma unroll
    for (int o = 0; o < NOUT; o++) {
        float s = v0 * Ws[o * D + lane] + v1 * Ws[o * D + lane + 32];
        s = wsum32(s);
        if (lane == o) res = s;
    }
    if (lane < NOUT) out[gw * NOUT + lane] = res + bs[lane];
}

// ---------------- launch ----------------
extern "C" void kernel_launch(void* const* d_in, const int* in_sizes, int n_in,
                              void* d_out, int out_size)
{
    const float* x_paper   = (const float*)d_in[0];
    const float* x_author  = (const float*)d_in[1];
    const float* x_subject = (const float*)d_in[2];
    const float* fc1p_w = (const float*)d_in[3];
    const float* fc1p_b = (const float*)d_in[4];
    const float* fc1a_w = (const float*)d_in[5];
    const float* fc1a_b = (const float*)d_in[6];
    const float* fc1s_w = (const float*)d_in[7];
    const float* fc1s_b = (const float*)d_in[8];
    const float* attn1  = (const float*)d_in[9];
    const float* attn2  = (const float*)d_in[10];
    const float* lw     = (const float*)d_in[11];
    const float* fc2_w  = (const float*)d_in[12];
    const float* fc2_b  = (const float*)d_in[13];
    const int* ei_pa = (const int*)d_in[14];
    const int* ei_ap = (const int*)d_in[15];
    const int* ei_ps = (const int*)d_in[16];
    const int* ei_sp = (const int*)d_in[17];
    float* out = (float*)d_out;

    zero_rowptr_kernel<<<(RP_TOT + 255) / 256, 256>>>();

    fc1_kernel<<<(NP  + 127) / 128, 256>>>(x_paper,   fc1p_w, fc1p_b, NP,  512, 0);
    fc1_kernel<<<(NA  + 127) / 128, 256>>>(x_author,  fc1a_w, fc1a_b, NA,  256, NP);
    fc1_kernel<<<(NSU + 127) / 128, 256>>>(x_subject, fc1s_w, fc1s_b, NSU, 128, NP + NA);

    hist_kernel<<<(E_TOT + 255) / 256, 256>>>(ei_pa, ei_ap, ei_ps, ei_sp);
    scan_kernel<<<4, 1024>>>();
    scatter_kernel<<<(E_TOT + 255) / 256, 256>>>(ei_pa, ei_ap, ei_ps, ei_sp);

    for (int hop = 0; hop < HOPS; hop++) {
        int curB = hop & 1;
        h1_kernel  <<<(H1_TOT * 32 + 255) / 256, 256>>>(attn2, hop, curB);
        aggr_kernel<<<(NTOT   * 32 + 255) / 256, 256>>>(attn1, attn2, lw, hop, curB);
    }

    fc2_kernel<<<(NP * 32 + 255) / 256, 256>>>(fc2_w, fc2_b, out);
}